// round 1
// baseline (speedup 1.0000x reference)
#include <cuda_runtime.h>
#include <cstddef>

// ---------------------------------------------------------------------------
// DaConA: pred = MLP(concat(u_indep[r], i_indep[c], (Wt@u[r]+bt)*(Wt@i[c]+bt)))
// Restructure: precompute TU = user_inter@Wt^T+bt (100k rows) and
// TI = item_inter@Wt^T+bt (50k rows) ONCE per launch instead of per batch
// element (262144 rows) -> 1.75x less transfer FLOPs and dense GEMMs.
// ---------------------------------------------------------------------------

#define NB      131072
#define NUSERS  100000
#define NITEMS  50000
#define DIMC    960
#define DIMS    32

// Scratch (no cudaMalloc allowed) — ~1.6 GB of __device__ globals.
__device__ float g_TU[(size_t)NUSERS * DIMC];
__device__ float g_TI[(size_t)NITEMS * DIMC];
__device__ float g_F0[(size_t)NB * 1024];
__device__ float g_F1[(size_t)NB * 512];
__device__ float g_F2[(size_t)NB * 256];
__device__ float g_F3[(size_t)NB * 128];

// ---------------------------------------------------------------------------
// NT SGEMM: C[m][n] = act( sum_k A[m][k] * Bw[n][k] + bias[n] )
// A: [M,K] row-major, Bw: [N,K] row-major (torch Linear weight layout).
// 128x128 block tile, BK=16, 256 threads, 8x8 microtile.
// ---------------------------------------------------------------------------
template<bool TANH>
__global__ __launch_bounds__(256) void gemm_nt(
    const float* __restrict__ A, const float* __restrict__ Bw,
    const float* __restrict__ bias, float* __restrict__ C,
    int M, int N, int K)
{
    __shared__ float As[16][128];
    __shared__ float Bs[16][128];

    const int bm = blockIdx.y * 128;
    const int bn = blockIdx.x * 128;
    const int t  = threadIdx.x;
    const int tx = t & 15;
    const int ty = t >> 4;

    float acc[8][8];
#pragma unroll
    for (int i = 0; i < 8; i++)
#pragma unroll
        for (int j = 0; j < 8; j++) acc[i][j] = 0.f;

    for (int k0 = 0; k0 < K; k0 += 16) {
#pragma unroll
        for (int l = 0; l < 2; l++) {
            int fidx = t + l * 256;          // 512 float4 per operand tile
            int row  = fidx >> 2;            // 0..127
            int q    = (fidx & 3) * 4;       // 0,4,8,12

            float4 av = make_float4(0.f, 0.f, 0.f, 0.f);
            int gr = bm + row;
            if (gr < M) av = *(const float4*)(A + (size_t)gr * K + k0 + q);
            As[q + 0][row] = av.x; As[q + 1][row] = av.y;
            As[q + 2][row] = av.z; As[q + 3][row] = av.w;

            float4 bv = make_float4(0.f, 0.f, 0.f, 0.f);
            int gn = bn + row;
            if (gn < N) bv = *(const float4*)(Bw + (size_t)gn * K + k0 + q);
            Bs[q + 0][row] = bv.x; Bs[q + 1][row] = bv.y;
            Bs[q + 2][row] = bv.z; Bs[q + 3][row] = bv.w;
        }
        __syncthreads();

#pragma unroll
        for (int kk = 0; kk < 16; kk++) {
            float a[8], b[8];
            *(float4*)&a[0] = *(const float4*)&As[kk][ty * 4];
            *(float4*)&a[4] = *(const float4*)&As[kk][64 + ty * 4];
            *(float4*)&b[0] = *(const float4*)&Bs[kk][tx * 4];
            *(float4*)&b[4] = *(const float4*)&Bs[kk][64 + tx * 4];
#pragma unroll
            for (int i = 0; i < 8; i++)
#pragma unroll
                for (int j = 0; j < 8; j++)
                    acc[i][j] = fmaf(a[i], b[j], acc[i][j]);
        }
        __syncthreads();
    }

#pragma unroll
    for (int i = 0; i < 8; i++) {
        int gm = bm + (i < 4 ? ty * 4 + i : 64 + ty * 4 + (i - 4));
        if (gm >= M) continue;
#pragma unroll
        for (int j = 0; j < 8; j++) {
            int gn = bn + (j < 4 ? tx * 4 + j : 64 + tx * 4 + (j - 4));
            if (gn >= N) continue;
            float v = acc[i][j] + bias[gn];
            if (TANH) v = tanhf(v);
            C[(size_t)gm * N + gn] = v;
        }
    }
}

// ---------------------------------------------------------------------------
// Build factor matrix F0[b, 0:32]=u_indep[r], [32:64]=i_indep[c],
// [64:1024]=TU[r]*TI[c].  One block per batch row, one float4 per thread.
// ---------------------------------------------------------------------------
__global__ __launch_bounds__(256) void build_factor(
    const int* __restrict__ rows, const int* __restrict__ cols,
    const float* __restrict__ uix, const float* __restrict__ iix,
    const float* __restrict__ TU, const float* __restrict__ TI,
    float* __restrict__ F0)
{
    const int b = blockIdx.x;
    const int r = rows[b];
    const int c = cols[b];
    const int f = threadIdx.x * 4;

    float4 v;
    if (f < 32) {
        v = *(const float4*)(uix + (size_t)r * DIMS + f);
    } else if (f < 64) {
        v = *(const float4*)(iix + (size_t)c * DIMS + (f - 32));
    } else {
        float4 a  = *(const float4*)(TU + (size_t)r * DIMC + (f - 64));
        float4 bb = *(const float4*)(TI + (size_t)c * DIMC + (f - 64));
        v = make_float4(a.x * bb.x, a.y * bb.y, a.z * bb.z, a.w * bb.w);
    }
    *(float4*)(F0 + (size_t)b * 1024 + f) = v;
}

// ---------------------------------------------------------------------------
// Final dot: out[b] = F3[b] . Wr + br + 3.5.  One warp per batch row.
// ---------------------------------------------------------------------------
__global__ __launch_bounds__(256) void final_dot(
    const float* __restrict__ F3, const float* __restrict__ Wr,
    const float* __restrict__ br, float* __restrict__ out, int Bn)
{
    __shared__ float w[128];
    const int t = threadIdx.x;
    if (t < 128) w[t] = Wr[t];
    __syncthreads();

    const int warp = t >> 5, lane = t & 31;
    const int b = blockIdx.x * 8 + warp;
    if (b >= Bn) return;

    float4 v  = *(const float4*)(F3 + (size_t)b * 128 + lane * 4);
    float4 wv = *(const float4*)&w[lane * 4];
    float s = v.x * wv.x + v.y * wv.y + v.z * wv.z + v.w * wv.w;
#pragma unroll
    for (int o = 16; o; o >>= 1) s += __shfl_xor_sync(0xFFFFFFFFu, s, o);
    if (lane == 0) out[b] = s + br[0] + 3.5f;
}

// ---------------------------------------------------------------------------
extern "C" void kernel_launch(void* const* d_in, const int* in_sizes, int n_in,
                              void* d_out, int out_size)
{
    const int*   rows       = (const int*)d_in[0];
    const int*   cols       = (const int*)d_in[1];
    const float* user_inter = (const float*)d_in[2];
    const float* item_inter = (const float*)d_in[3];
    const float* uix        = (const float*)d_in[4];
    const float* iix        = (const float*)d_in[5];
    const float* Wt         = (const float*)d_in[6];
    const float* bt         = (const float*)d_in[7];
    const float* W1         = (const float*)d_in[8];
    const float* b1         = (const float*)d_in[9];
    const float* W2         = (const float*)d_in[10];
    const float* b2         = (const float*)d_in[11];
    const float* W3         = (const float*)d_in[12];
    const float* b3         = (const float*)d_in[13];
    const float* Wr         = (const float*)d_in[14];
    const float* br         = (const float*)d_in[15];
    float*       out        = (float*)d_out;

    float *TU, *TI, *F0, *F1, *F2, *F3;
    cudaGetSymbolAddress((void**)&TU, g_TU);
    cudaGetSymbolAddress((void**)&TI, g_TI);
    cudaGetSymbolAddress((void**)&F0, g_F0);
    cudaGetSymbolAddress((void**)&F1, g_F1);
    cudaGetSymbolAddress((void**)&F2, g_F2);
    cudaGetSymbolAddress((void**)&F3, g_F3);

    const dim3 blk(256);

    // 1) Per-entity transfer transforms (dense NT GEMMs, no tanh)
    gemm_nt<false><<<dim3((DIMC + 127) / 128, (NUSERS + 127) / 128), blk>>>(
        user_inter, Wt, bt, TU, NUSERS, DIMC, DIMC);
    gemm_nt<false><<<dim3((DIMC + 127) / 128, (NITEMS + 127) / 128), blk>>>(
        item_inter, Wt, bt, TI, NITEMS, DIMC, DIMC);

    // 2) Gather + elementwise product + concat
    build_factor<<<NB, blk>>>(rows, cols, uix, iix, TU, TI, F0);

    // 3) MLP layers (tanh epilogue)
    gemm_nt<true><<<dim3(512 / 128, NB / 128), blk>>>(F0, W1, b1, F1, NB, 512, 1024);
    gemm_nt<true><<<dim3(256 / 128, NB / 128), blk>>>(F1, W2, b2, F2, NB, 256, 512);
    gemm_nt<true><<<dim3(128 / 128, NB / 128), blk>>>(F2, W3, b3, F3, NB, 128, 256);

    // 4) Final projection + global average
    final_dot<<<NB / 8, blk>>>(F3, Wr, br, out, NB);
}

// round 3
// speedup vs baseline: 3.7911x; 3.7911x over previous
#include <cuda_runtime.h>
#include <cstdint>
#include <cstddef>

// ===========================================================================
// DaConA on GB300 (PTX target sm_103: no tcgen05 -> use mma.sync tf32 HMMA).
// pred = MLP(concat(u_indep[r], i_indep[c], (Wt@u[r]+bt)*(Wt@i[c]+bt))) + 3.5
// TU/TI precomputed per-entity (1.75x fewer transfer FLOPs than per-batch).
// ===========================================================================

#define NB      131072
#define NUSERS  100000
#define NITEMS  50000
#define DIMC    960
#define DIMS    32

__device__ float g_TU[(size_t)NUSERS * DIMC];
__device__ float g_TI[(size_t)NITEMS * DIMC];
__device__ float g_F0[(size_t)NB * 1024];
__device__ float g_F1[(size_t)NB * 512];
__device__ float g_F2[(size_t)NB * 256];
__device__ float g_F3[(size_t)NB * 128];

__device__ __forceinline__ uint32_t smem_u32(const void* p) {
    uint32_t a;
    asm("{ .reg .u64 t; cvta.to.shared.u64 t, %1; cvt.u32.u64 %0, t; }" : "=r"(a) : "l"(p));
    return a;
}
#define SWZ128(o) ((o) ^ (((o) >> 3) & 0x70))

__device__ __forceinline__ void cp16(uint32_t dst, const float* src, uint32_t sz) {
    asm volatile("cp.async.cg.shared.global [%0], [%1], 16, %2;" :: "r"(dst), "l"(src), "r"(sz));
}
__device__ __forceinline__ uint32_t lds32(uint32_t a) {
    uint32_t v;
    asm volatile("ld.shared.b32 %0, [%1];" : "=r"(v) : "r"(a));
    return v;
}
// D(16x8) += A(16x8,row) * B(8x8,col) ; tf32 inputs, f32 accum
__device__ __forceinline__ void mma8(float* d, const uint32_t* a, const uint32_t* b) {
    asm volatile("mma.sync.aligned.m16n8k8.row.col.f32.tf32.tf32.f32 "
                 "{%0,%1,%2,%3}, {%4,%5,%6,%7}, {%8,%9}, {%0,%1,%2,%3};"
                 : "+f"(d[0]), "+f"(d[1]), "+f"(d[2]), "+f"(d[3])
                 : "r"(a[0]), "r"(a[1]), "r"(a[2]), "r"(a[3]), "r"(b[0]), "r"(b[1]));
}

// ---------------------------------------------------------------------------
// tf32 mma.sync NT GEMM: C[m][n] = act( sum_k A[m][k]*Bw[n][k] + bias[n] )
// BM=BN=128, BK=32 floats (=128B SW128 rows), 3-stage cp.async pipeline.
// 8 warps: 2(m) x 4(n); warp tile 64x32; 4x4 m16n8k8 tiles per k-step.
// ---------------------------------------------------------------------------
template<bool TANH>
__global__ __launch_bounds__(256) void gemm_tc(
    const float* __restrict__ A, const float* __restrict__ Bw,
    const float* __restrict__ bias, float* __restrict__ C,
    int M, int N, int K)
{
    extern __shared__ char smem[];
    const uint32_t base = smem_u32(smem);
    const int t = threadIdx.x;
    const int wid = t >> 5, lane = t & 31;
    const int wm = wid >> 2;            // 0..1  (64-row half)
    const int wn = wid & 3;             // 0..3  (32-col quarter)
    const int g  = lane >> 2;           // 0..7
    const int q  = lane & 3;            // 0..3

    constexpr int TILE = 16384;         // 128 rows x 128 B
    constexpr int SB   = 2 * TILE;      // A tile + B tile per stage
    const int bm = blockIdx.y * 128;
    const int bn = blockIdx.x * 128;

    float* biass = (float*)(smem);
    const uint32_t tiles = (base + 1024 + 1023) & ~1023u;

    for (int j = t; j < 128; j += 256) {
        int gn = bn + j;
        biass[j] = (gn < N) ? bias[gn] : 0.f;
    }

    const int seg = t & 7;              // 16B segment in a 128B row
    const int rb  = t >> 3;             // 0..31

    auto load_chunk = [&](int c, int s) {
        const uint32_t at = tiles + s * SB;
        const uint32_t bt_ = at + TILE;
#pragma unroll
        for (int rr = 0; rr < 4; rr++) {
            int row = rb + rr * 32;
            int gr  = bm + row;
            int ok  = gr < M;
            const float* src = A + (size_t)(ok ? gr : 0) * K + c * 32 + seg * 4;
            cp16(at + SWZ128(row * 128 + seg * 16), src, ok ? 16u : 0u);
        }
#pragma unroll
        for (int rr = 0; rr < 4; rr++) {
            int row = rb + rr * 32;
            int gn  = bn + row;
            int ok  = gn < N;
            const float* src = Bw + (size_t)(ok ? gn : 0) * K + c * 32 + seg * 4;
            cp16(bt_ + SWZ128(row * 128 + seg * 16), src, ok ? 16u : 0u);
        }
        asm volatile("cp.async.commit_group;" ::: "memory");
    };

    float acc[4][4][4];
#pragma unroll
    for (int i = 0; i < 4; i++)
#pragma unroll
        for (int j = 0; j < 4; j++)
#pragma unroll
            for (int v = 0; v < 4; v++) acc[i][j][v] = 0.f;

    const int NKc = K >> 5;             // K/32, all layers divisible
    load_chunk(0, 0);
    load_chunk(1, 1);

    for (int i = 0; i < NKc; i++) {
        const int s = i - (i / 3) * 3;  // i % 3
        if (i + 1 < NKc) asm volatile("cp.async.wait_group 1;" ::: "memory");
        else             asm volatile("cp.async.wait_group 0;" ::: "memory");
        __syncthreads();
        if (i + 2 < NKc) {
            int s2 = i + 2; s2 -= (s2 / 3) * 3;
            load_chunk(i + 2, s2);
        }

        const uint32_t a_s = tiles + s * SB;
        const uint32_t b_s = a_s + TILE;
#pragma unroll
        for (int ks = 0; ks < 4; ks++) {
            uint32_t af[4][4], bf[4][2];
            const int kc = ks * 32 + q * 4;       // byte col offset of a0/b0
#pragma unroll
            for (int mt = 0; mt < 4; mt++) {
                const int r0 = (wm * 64 + mt * 16 + g) * 128;
                af[mt][0] = lds32(a_s + SWZ128(r0 + kc));
                af[mt][1] = lds32(a_s + SWZ128(r0 + 1024 + kc));
                af[mt][2] = lds32(a_s + SWZ128(r0 + kc + 16));
                af[mt][3] = lds32(a_s + SWZ128(r0 + 1024 + kc + 16));
            }
#pragma unroll
            for (int nt = 0; nt < 4; nt++) {
                const int r0 = (wn * 32 + nt * 8 + g) * 128;
                bf[nt][0] = lds32(b_s + SWZ128(r0 + kc));
                bf[nt][1] = lds32(b_s + SWZ128(r0 + kc + 16));
            }
#pragma unroll
            for (int mt = 0; mt < 4; mt++)
#pragma unroll
                for (int nt = 0; nt < 4; nt++)
                    mma8(acc[mt][nt], af[mt], bf[nt]);
        }
    }
    __syncthreads();

    // Epilogue: bias + optional tanh, float2 stores.
#pragma unroll
    for (int mt = 0; mt < 4; mt++) {
        const int r0 = bm + wm * 64 + mt * 16 + g;
#pragma unroll
        for (int nt = 0; nt < 4; nt++) {
            const int jc = wn * 32 + nt * 8 + 2 * q;   // col within block
            const int gn = bn + jc;
            if (gn >= N) continue;
            const float bx = biass[jc], by = biass[jc + 1];
            float x0 = acc[mt][nt][0] + bx, x1 = acc[mt][nt][1] + by;
            float x2 = acc[mt][nt][2] + bx, x3 = acc[mt][nt][3] + by;
            if (TANH) { x0 = tanhf(x0); x1 = tanhf(x1); x2 = tanhf(x2); x3 = tanhf(x3); }
            if (r0 < M)     *(float2*)(C + (size_t)r0 * N + gn)       = make_float2(x0, x1);
            if (r0 + 8 < M) *(float2*)(C + (size_t)(r0 + 8) * N + gn) = make_float2(x2, x3);
        }
    }
}

// ---------------------------------------------------------------------------
// Gather + elementwise product + concat into F0[B, 1024]
// ---------------------------------------------------------------------------
__global__ __launch_bounds__(256) void build_factor(
    const int* __restrict__ rows, const int* __restrict__ cols,
    const float* __restrict__ uix, const float* __restrict__ iix,
    const float* __restrict__ TU, const float* __restrict__ TI,
    float* __restrict__ F0)
{
    const int b = blockIdx.x;
    const int r = rows[b];
    const int c = cols[b];
    const int f = threadIdx.x * 4;

    float4 v;
    if (f < 32) {
        v = *(const float4*)(uix + (size_t)r * DIMS + f);
    } else if (f < 64) {
        v = *(const float4*)(iix + (size_t)c * DIMS + (f - 32));
    } else {
        float4 a  = *(const float4*)(TU + (size_t)r * DIMC + (f - 64));
        float4 bb = *(const float4*)(TI + (size_t)c * DIMC + (f - 64));
        v = make_float4(a.x * bb.x, a.y * bb.y, a.z * bb.z, a.w * bb.w);
    }
    *(float4*)(F0 + (size_t)b * 1024 + f) = v;
}

// ---------------------------------------------------------------------------
// out[b] = F3[b] . Wr + br + 3.5
// ---------------------------------------------------------------------------
__global__ __launch_bounds__(256) void final_dot(
    const float* __restrict__ F3, const float* __restrict__ Wr,
    const float* __restrict__ br, float* __restrict__ out, int Bn)
{
    __shared__ float w[128];
    const int t = threadIdx.x;
    if (t < 128) w[t] = Wr[t];
    __syncthreads();

    const int warp = t >> 5, lane = t & 31;
    const int b = blockIdx.x * 8 + warp;
    if (b >= Bn) return;

    float4 v  = *(const float4*)(F3 + (size_t)b * 128 + lane * 4);
    float4 wv = *(const float4*)&w[lane * 4];
    float s = v.x * wv.x + v.y * wv.y + v.z * wv.z + v.w * wv.w;
#pragma unroll
    for (int o = 16; o; o >>= 1) s += __shfl_xor_sync(0xFFFFFFFFu, s, o);
    if (lane == 0) out[b] = s + br[0] + 3.5f;
}

// ---------------------------------------------------------------------------
extern "C" void kernel_launch(void* const* d_in, const int* in_sizes, int n_in,
                              void* d_out, int out_size)
{
    const int*   rows       = (const int*)d_in[0];
    const int*   cols       = (const int*)d_in[1];
    const float* user_inter = (const float*)d_in[2];
    const float* item_inter = (const float*)d_in[3];
    const float* uix        = (const float*)d_in[4];
    const float* iix        = (const float*)d_in[5];
    const float* Wt         = (const float*)d_in[6];
    const float* bt         = (const float*)d_in[7];
    const float* W1         = (const float*)d_in[8];
    const float* b1         = (const float*)d_in[9];
    const float* W2         = (const float*)d_in[10];
    const float* b2         = (const float*)d_in[11];
    const float* W3         = (const float*)d_in[12];
    const float* b3         = (const float*)d_in[13];
    const float* Wr         = (const float*)d_in[14];
    const float* br         = (const float*)d_in[15];
    float*       out        = (float*)d_out;

    float *TU, *TI, *F0, *F1, *F2, *F3;
    cudaGetSymbolAddress((void**)&TU, g_TU);
    cudaGetSymbolAddress((void**)&TI, g_TI);
    cudaGetSymbolAddress((void**)&F0, g_F0);
    cudaGetSymbolAddress((void**)&F1, g_F1);
    cudaGetSymbolAddress((void**)&F2, g_F2);
    cudaGetSymbolAddress((void**)&F3, g_F3);

    // dyn smem: 1024 hdr (bias) + 1024 align slack + 3 stages * 32KB
    const int SZ = 1024 + 1024 + 3 * 32768;   // 100352
    cudaFuncSetAttribute(gemm_tc<false>, cudaFuncAttributeMaxDynamicSharedMemorySize, SZ);
    cudaFuncSetAttribute(gemm_tc<true>,  cudaFuncAttributeMaxDynamicSharedMemorySize, SZ);

    const dim3 blk(256);

    // 1) Per-entity transfer transforms: TU[100000,960], TI[50000,960], K=960
    gemm_tc<false><<<dim3(8, (NUSERS + 127) / 128), blk, SZ>>>(
        user_inter, Wt, bt, TU, NUSERS, DIMC, DIMC);
    gemm_tc<false><<<dim3(8, (NITEMS + 127) / 128), blk, SZ>>>(
        item_inter, Wt, bt, TI, NITEMS, DIMC, DIMC);

    // 2) Gather + elementwise product + concat
    build_factor<<<NB, blk>>>(rows, cols, uix, iix, TU, TI, F0);

    // 3) MLP layers (tanh epilogue)
    gemm_tc<true><<<dim3(4, NB / 128), blk, SZ>>>(F0, W1, b1, F1, NB, 512, 1024);
    gemm_tc<true><<<dim3(2, NB / 128), blk, SZ>>>(F1, W2, b2, F2, NB, 256, 512);
    gemm_tc<true><<<dim3(1, NB / 128), blk, SZ>>>(F2, W3, b3, F3, NB, 128, 256);

    // 4) Final projection + global average
    final_dot<<<NB / 8, blk>>>(F3, Wr, br, out, NB);
}

// round 4
// speedup vs baseline: 6.1209x; 1.6145x over previous
#include <cuda_runtime.h>
#include <cuda_bf16.h>
#include <cstdint>
#include <cstddef>

// ===========================================================================
// DaConA on GB300 (PTX target sm_103: no tcgen05 -> mma.sync bf16 HMMA k16).
// pred = MLP(concat(u_indep[r], i_indep[c], (Wt@u[r]+bt)*(Wt@i[c]+bt))) + 3.5
// TU/TI precomputed per-entity; all GEMMs bf16 inputs / fp32 accumulate.
// ===========================================================================

#define NB      131072
#define NUSERS  100000
#define NITEMS  50000
#define DIMC    960
#define DIMS    32

// fp32 scratch
__device__ float g_TU[(size_t)NUSERS * DIMC];
__device__ float g_TI[(size_t)NITEMS * DIMC];
// bf16 scratch
__device__ __nv_bfloat16 g_UIb[(size_t)NUSERS * DIMC];
__device__ __nv_bfloat16 g_IIb[(size_t)NITEMS * DIMC];
__device__ __nv_bfloat16 g_Wtb[(size_t)DIMC * DIMC];
__device__ __nv_bfloat16 g_W1b[512 * 1024];
__device__ __nv_bfloat16 g_W2b[256 * 512];
__device__ __nv_bfloat16 g_W3b[128 * 256];
__device__ __nv_bfloat16 g_F0[(size_t)NB * 1024];
__device__ __nv_bfloat16 g_F1[(size_t)NB * 512];
__device__ __nv_bfloat16 g_F2[(size_t)NB * 256];
__device__ __nv_bfloat16 g_F3[(size_t)NB * 128];

__device__ __forceinline__ uint32_t smem_u32(const void* p) {
    uint32_t a;
    asm("{ .reg .u64 t; cvta.to.shared.u64 t, %1; cvt.u32.u64 %0, t; }" : "=r"(a) : "l"(p));
    return a;
}
#define SWZ128(o) ((o) ^ (((o) >> 3) & 0x70))

__device__ __forceinline__ void cp16(uint32_t dst, const void* src, uint32_t sz) {
    asm volatile("cp.async.cg.shared.global [%0], [%1], 16, %2;" :: "r"(dst), "l"(src), "r"(sz));
}
__device__ __forceinline__ uint32_t lds32(uint32_t a) {
    uint32_t v;
    asm volatile("ld.shared.b32 %0, [%1];" : "=r"(v) : "r"(a));
    return v;
}
// D(16x8) += A(16x16,row) * B(16x8,col) ; bf16 inputs, f32 accum
__device__ __forceinline__ void mma16(float* d, const uint32_t* a, const uint32_t* b) {
    asm volatile("mma.sync.aligned.m16n8k16.row.col.f32.bf16.bf16.f32 "
                 "{%0,%1,%2,%3}, {%4,%5,%6,%7}, {%8,%9}, {%0,%1,%2,%3};"
                 : "+f"(d[0]), "+f"(d[1]), "+f"(d[2]), "+f"(d[3])
                 : "r"(a[0]), "r"(a[1]), "r"(a[2]), "r"(a[3]), "r"(b[0]), "r"(b[1]));
}

// ---------------------------------------------------------------------------
// bf16 mma.sync NT GEMM: C[m][n] = act( sum_k A[m][k]*Bw[n][k] + bias[n] )
// BM=BN=128, BK=64 bf16 (=128B SW128 rows), 3-stage cp.async pipeline.
// 8 warps: 2(m) x 4(n); warp tile 64x32; 4x4 m16n8k16 tiles per k-chunk.
// ---------------------------------------------------------------------------
template<bool TANH, bool OUT_BF16>
__global__ __launch_bounds__(256) void gemm_bf(
    const __nv_bfloat16* __restrict__ A, const __nv_bfloat16* __restrict__ Bw,
    const float* __restrict__ bias, void* __restrict__ Cv,
    int M, int N, int K)
{
    extern __shared__ char smem[];
    const uint32_t base = smem_u32(smem);
    const int t = threadIdx.x;
    const int wid = t >> 5, lane = t & 31;
    const int wm = wid >> 2;            // 0..1  (64-row half)
    const int wn = wid & 3;             // 0..3  (32-col quarter)
    const int g  = lane >> 2;           // 0..7
    const int q  = lane & 3;            // 0..3

    constexpr int TILE = 16384;         // 128 rows x 128 B
    constexpr int SB   = 2 * TILE;      // A tile + B tile per stage
    const int bm = blockIdx.y * 128;
    const int bn = blockIdx.x * 128;

    float* biass = (float*)(smem);
    const uint32_t tiles = (base + 1024 + 1023) & ~1023u;

    for (int j = t; j < 128; j += 256) {
        int gn = bn + j;
        biass[j] = (gn < N) ? bias[gn] : 0.f;
    }

    const int seg = t & 7;              // 16B segment in a 128B row (8 bf16)
    const int rb  = t >> 3;             // 0..31

    auto load_chunk = [&](int c, int s) {
        const uint32_t at = tiles + s * SB;
        const uint32_t bt_ = at + TILE;
#pragma unroll
        for (int rr = 0; rr < 4; rr++) {
            int row = rb + rr * 32;
            int gr  = bm + row;
            int ok  = gr < M;
            const __nv_bfloat16* src = A + (size_t)(ok ? gr : 0) * K + c * 64 + seg * 8;
            cp16(at + SWZ128(row * 128 + seg * 16), src, ok ? 16u : 0u);
        }
#pragma unroll
        for (int rr = 0; rr < 4; rr++) {
            int row = rb + rr * 32;
            int gn  = bn + row;
            int ok  = gn < N;
            const __nv_bfloat16* src = Bw + (size_t)(ok ? gn : 0) * K + c * 64 + seg * 8;
            cp16(bt_ + SWZ128(row * 128 + seg * 16), src, ok ? 16u : 0u);
        }
        asm volatile("cp.async.commit_group;" ::: "memory");
    };

    float acc[4][4][4];
#pragma unroll
    for (int i = 0; i < 4; i++)
#pragma unroll
        for (int j = 0; j < 4; j++)
#pragma unroll
            for (int v = 0; v < 4; v++) acc[i][j][v] = 0.f;

    const int NKc = K >> 6;             // K/64 bf16 elems per chunk
    load_chunk(0, 0);
    load_chunk(1, 1);

    for (int i = 0; i < NKc; i++) {
        const int s = i - (i / 3) * 3;  // i % 3
        if (i + 1 < NKc) asm volatile("cp.async.wait_group 1;" ::: "memory");
        else             asm volatile("cp.async.wait_group 0;" ::: "memory");
        __syncthreads();
        if (i + 2 < NKc) {
            int s2 = i + 2; s2 -= (s2 / 3) * 3;
            load_chunk(i + 2, s2);
        }

        const uint32_t a_s = tiles + s * SB;
        const uint32_t b_s = a_s + TILE;
#pragma unroll
        for (int ks = 0; ks < 4; ks++) {        // 4 x k16 per 128B chunk
            uint32_t af[4][4], bf[4][2];
            const int kc = ks * 32 + q * 4;     // byte col offset of a0/b0
#pragma unroll
            for (int mt = 0; mt < 4; mt++) {
                const int r0 = (wm * 64 + mt * 16 + g) * 128;
                af[mt][0] = lds32(a_s + SWZ128(r0 + kc));
                af[mt][1] = lds32(a_s + SWZ128(r0 + 1024 + kc));
                af[mt][2] = lds32(a_s + SWZ128(r0 + kc + 16));
                af[mt][3] = lds32(a_s + SWZ128(r0 + 1024 + kc + 16));
            }
#pragma unroll
            for (int nt = 0; nt < 4; nt++) {
                const int r0 = (wn * 32 + nt * 8 + g) * 128;
                bf[nt][0] = lds32(b_s + SWZ128(r0 + kc));
                bf[nt][1] = lds32(b_s + SWZ128(r0 + kc + 16));
            }
#pragma unroll
            for (int mt = 0; mt < 4; mt++)
#pragma unroll
                for (int nt = 0; nt < 4; nt++)
                    mma16(acc[mt][nt], af[mt], bf[nt]);
        }
    }
    __syncthreads();

    // Epilogue: bias + optional tanh; bf16x2 or float2 stores.
#pragma unroll
    for (int mt = 0; mt < 4; mt++) {
        const int r0 = bm + wm * 64 + mt * 16 + g;
#pragma unroll
        for (int nt = 0; nt < 4; nt++) {
            const int jc = wn * 32 + nt * 8 + 2 * q;   // col within block
            const int gn = bn + jc;
            if (gn >= N) continue;
            const float bx = biass[jc], by = biass[jc + 1];
            float x0 = acc[mt][nt][0] + bx, x1 = acc[mt][nt][1] + by;
            float x2 = acc[mt][nt][2] + bx, x3 = acc[mt][nt][3] + by;
            if (TANH) { x0 = tanhf(x0); x1 = tanhf(x1); x2 = tanhf(x2); x3 = tanhf(x3); }
            if (OUT_BF16) {
                __nv_bfloat16* C = (__nv_bfloat16*)Cv;
                if (r0 < M)
                    *(__nv_bfloat162*)(C + (size_t)r0 * N + gn) =
                        __nv_bfloat162(__float2bfloat16(x0), __float2bfloat16(x1));
                if (r0 + 8 < M)
                    *(__nv_bfloat162*)(C + (size_t)(r0 + 8) * N + gn) =
                        __nv_bfloat162(__float2bfloat16(x2), __float2bfloat16(x3));
            } else {
                float* C = (float*)Cv;
                if (r0 < M)     *(float2*)(C + (size_t)r0 * N + gn)       = make_float2(x0, x1);
                if (r0 + 8 < M) *(float2*)(C + (size_t)(r0 + 8) * N + gn) = make_float2(x2, x3);
            }
        }
    }
}

// ---------------------------------------------------------------------------
// fp32 -> bf16 conversion (n divisible by 1024; 4 elems/thread)
// ---------------------------------------------------------------------------
__global__ __launch_bounds__(256) void conv_bf16(
    const float* __restrict__ in, __nv_bfloat16* __restrict__ out)
{
    const size_t i = ((size_t)blockIdx.x * 256 + threadIdx.x) * 4;
    float4 v = *(const float4*)(in + i);
    __nv_bfloat162 lo(__float2bfloat16(v.x), __float2bfloat16(v.y));
    __nv_bfloat162 hi(__float2bfloat16(v.z), __float2bfloat16(v.w));
    *(__nv_bfloat162*)(out + i)     = lo;
    *(__nv_bfloat162*)(out + i + 2) = hi;
}

// ---------------------------------------------------------------------------
// Gather + elementwise product + concat into F0[B, 1024] (bf16)
// ---------------------------------------------------------------------------
__global__ __launch_bounds__(256) void build_factor(
    const int* __restrict__ rows, const int* __restrict__ cols,
    const float* __restrict__ uix, const float* __restrict__ iix,
    const float* __restrict__ TU, const float* __restrict__ TI,
    __nv_bfloat16* __restrict__ F0)
{
    const int b = blockIdx.x;
    const int r = rows[b];
    const int c = cols[b];
    const int f = threadIdx.x * 4;

    float4 v;
    if (f < 32) {
        v = *(const float4*)(uix + (size_t)r * DIMS + f);
    } else if (f < 64) {
        v = *(const float4*)(iix + (size_t)c * DIMS + (f - 32));
    } else {
        float4 a  = *(const float4*)(TU + (size_t)r * DIMC + (f - 64));
        float4 bb = *(const float4*)(TI + (size_t)c * DIMC + (f - 64));
        v = make_float4(a.x * bb.x, a.y * bb.y, a.z * bb.z, a.w * bb.w);
    }
    __nv_bfloat16* o = F0 + (size_t)b * 1024 + f;
    *(__nv_bfloat162*)(o)     = __nv_bfloat162(__float2bfloat16(v.x), __float2bfloat16(v.y));
    *(__nv_bfloat162*)(o + 2) = __nv_bfloat162(__float2bfloat16(v.z), __float2bfloat16(v.w));
}

// ---------------------------------------------------------------------------
// out[b] = F3[b] . Wr + br + 3.5   (F3 bf16)
// ---------------------------------------------------------------------------
__global__ __launch_bounds__(256) void final_dot(
    const __nv_bfloat16* __restrict__ F3, const float* __restrict__ Wr,
    const float* __restrict__ br, float* __restrict__ out, int Bn)
{
    __shared__ float w[128];
    const int t = threadIdx.x;
    if (t < 128) w[t] = Wr[t];
    __syncthreads();

    const int warp = t >> 5, lane = t & 31;
    const int b = blockIdx.x * 8 + warp;
    if (b >= Bn) return;

    const __nv_bfloat162* p = (const __nv_bfloat162*)(F3 + (size_t)b * 128 + lane * 4);
    float2 v0 = __bfloat1622float2(p[0]);
    float2 v1 = __bfloat1622float2(p[1]);
    float4 wv = *(const float4*)&w[lane * 4];
    float s = v0.x * wv.x + v0.y * wv.y + v1.x * wv.z + v1.y * wv.w;
#pragma unroll
    for (int o = 16; o; o >>= 1) s += __shfl_xor_sync(0xFFFFFFFFu, s, o);
    if (lane == 0) out[b] = s + br[0] + 3.5f;
}

// ---------------------------------------------------------------------------
extern "C" void kernel_launch(void* const* d_in, const int* in_sizes, int n_in,
                              void* d_out, int out_size)
{
    const int*   rows       = (const int*)d_in[0];
    const int*   cols       = (const int*)d_in[1];
    const float* user_inter = (const float*)d_in[2];
    const float* item_inter = (const float*)d_in[3];
    const float* uix        = (const float*)d_in[4];
    const float* iix        = (const float*)d_in[5];
    const float* Wt         = (const float*)d_in[6];
    const float* bt         = (const float*)d_in[7];
    const float* W1         = (const float*)d_in[8];
    const float* b1         = (const float*)d_in[9];
    const float* W2         = (const float*)d_in[10];
    const float* b2         = (const float*)d_in[11];
    const float* W3         = (const float*)d_in[12];
    const float* b3         = (const float*)d_in[13];
    const float* Wr         = (const float*)d_in[14];
    const float* br         = (const float*)d_in[15];
    float*       out        = (float*)d_out;

    float *TU, *TI;
    __nv_bfloat16 *UIb, *IIb, *Wtb, *W1b, *W2b, *W3b, *F0, *F1, *F2, *F3;
    cudaGetSymbolAddress((void**)&TU, g_TU);
    cudaGetSymbolAddress((void**)&TI, g_TI);
    cudaGetSymbolAddress((void**)&UIb, g_UIb);
    cudaGetSymbolAddress((void**)&IIb, g_IIb);
    cudaGetSymbolAddress((void**)&Wtb, g_Wtb);
    cudaGetSymbolAddress((void**)&W1b, g_W1b);
    cudaGetSymbolAddress((void**)&W2b, g_W2b);
    cudaGetSymbolAddress((void**)&W3b, g_W3b);
    cudaGetSymbolAddress((void**)&F0, g_F0);
    cudaGetSymbolAddress((void**)&F1, g_F1);
    cudaGetSymbolAddress((void**)&F2, g_F2);
    cudaGetSymbolAddress((void**)&F3, g_F3);

    const int SZ = 1024 + 1024 + 3 * 32768;   // 100352
    cudaFuncSetAttribute(gemm_bf<false, false>, cudaFuncAttributeMaxDynamicSharedMemorySize, SZ);
    cudaFuncSetAttribute(gemm_bf<true, true>,   cudaFuncAttributeMaxDynamicSharedMemorySize, SZ);

    const dim3 blk(256);

    // 0) fp32 -> bf16 conversions (all sizes divisible by 1024)
    conv_bf16<<<(NUSERS * DIMC) / 1024, blk>>>(user_inter, UIb);
    conv_bf16<<<(NITEMS * DIMC) / 1024, blk>>>(item_inter, IIb);
    conv_bf16<<<(DIMC * DIMC) / 1024, blk>>>(Wt, Wtb);
    conv_bf16<<<(512 * 1024) / 1024, blk>>>(W1, W1b);
    conv_bf16<<<(256 * 512) / 1024, blk>>>(W2, W2b);
    conv_bf16<<<(128 * 256) / 1024, blk>>>(W3, W3b);

    // 1) Per-entity transfer transforms (fp32 out)
    gemm_bf<false, false><<<dim3(8, (NUSERS + 127) / 128), blk, SZ>>>(
        UIb, Wtb, bt, TU, NUSERS, DIMC, DIMC);
    gemm_bf<false, false><<<dim3(8, (NITEMS + 127) / 128), blk, SZ>>>(
        IIb, Wtb, bt, TI, NITEMS, DIMC, DIMC);

    // 2) Gather + elementwise product + concat (bf16 out)
    build_factor<<<NB, blk>>>(rows, cols, uix, iix, TU, TI, F0);

    // 3) MLP layers (tanh epilogue, bf16 out)
    gemm_bf<true, true><<<dim3(4, NB / 128), blk, SZ>>>(F0, W1b, b1, F1, NB, 512, 1024);
    gemm_bf<true, true><<<dim3(2, NB / 128), blk, SZ>>>(F1, W2b, b2, F2, NB, 256, 512);
    gemm_bf<true, true><<<dim3(1, NB / 128), blk, SZ>>>(F2, W3b, b3, F3, NB, 128, 256);

    // 4) Final projection + global average
    final_dot<<<NB / 8, blk>>>(F3, Wr, br, out, NB);
}